// round 14
// baseline (speedup 1.0000x reference)
#include <cuda_runtime.h>
#include <cuda_fp16.h>
#include <math.h>

#define T_TOK 2048
#define H_DIM 512
#define I_DIM 512
#define E_NUM 8
#define KTOP  4
#define BK    64
#define KPAD  8
#define LDH   (BK + KPAD)                 // 72 halves = 144 B row stride
#define ATILE_BYTES (128 * LDH * 2)       // 18432
#define STAGE_BYTES (2 * ATILE_BYTES)     // A + B per stage = 36864
#define NSTAGE 3
#define SMEM_DYN (NSTAGE * STAGE_BYTES)   // 110592

// ---------------- scratch (device globals, no allocs) ----------------
__device__ __half g_th [T_TOK * H_DIM];                       // RMSNorm out fp16 (gemm1 A)
__device__ __half g_w1h[(size_t)E_NUM * 2 * I_DIM * H_DIM];   // W1 fp16
__device__ __half g_w2h[(size_t)E_NUM * H_DIM * I_DIM];       // W2 fp16
__device__ __half g_ah [(size_t)E_NUM * T_TOK * I_DIM];       // SwiGLU activations fp16
__device__ int    g_cnt[E_NUM];
__device__ int    g_tok[E_NUM * T_TOK];
__device__ float  g_cw [E_NUM * T_TOK];
__device__ float  g_sumP[E_NUM];
__device__ float  g_imp [E_NUM];
__device__ float  g_wc  [E_NUM];

// ---------------- PTX helpers (base compute_103 target: HMMA + LDSM + cp.async) ----------------
__device__ __forceinline__ unsigned smem_u32(const void* p) {
    unsigned r;
    asm("{ .reg .u64 t; cvta.to.shared.u64 t, %1; cvt.u32.u64 %0, t; }" : "=r"(r) : "l"(p));
    return r;
}
__device__ __forceinline__ void cp16(unsigned saddr, const void* gaddr) {
    asm volatile("cp.async.cg.shared.global [%0], [%1], 16;" :: "r"(saddr), "l"(gaddr));
}
__device__ __forceinline__ void cp_commit() {
    asm volatile("cp.async.commit_group;" ::: "memory");
}
__device__ __forceinline__ void ldsm_x4(unsigned& r0, unsigned& r1, unsigned& r2, unsigned& r3,
                                        unsigned addr) {
    asm volatile("ldmatrix.sync.aligned.m8n8.x4.shared.b16 {%0,%1,%2,%3}, [%4];"
                 : "=r"(r0), "=r"(r1), "=r"(r2), "=r"(r3) : "r"(addr));
}
__device__ __forceinline__ void hmma(float* c, const unsigned* a, const unsigned* b) {
    asm volatile("mma.sync.aligned.m16n8k16.row.col.f32.f16.f16.f32 "
                 "{%0,%1,%2,%3}, {%4,%5,%6,%7}, {%8,%9}, {%0,%1,%2,%3};"
                 : "+f"(c[0]), "+f"(c[1]), "+f"(c[2]), "+f"(c[3])
                 : "r"(a[0]), "r"(a[1]), "r"(a[2]), "r"(a[3]), "r"(b[0]), "r"(b[1]));
}
__device__ __forceinline__ void red_v2(float* gaddr, float v0, float v1) {
    asm volatile("red.global.add.v2.f32 [%0], {%1, %2};"
                 :: "l"(gaddr), "f"(v0), "f"(v1) : "memory");
}

// ---------------- init: zero accumulators (tiny) ----------------
__global__ void init_kernel() {
    if (threadIdx.x < E_NUM) {
        g_cnt[threadIdx.x]  = 0;
        g_sumP[threadIdx.x] = 0.f;
        g_imp[threadIdx.x]  = 0.f;
        g_wc[threadIdx.x]   = 0.f;
    }
}

// ---------------- fused RMSNorm + gating + out=x + weight conversion ----------------
#define N4_W1 ((E_NUM * 2 * I_DIM * H_DIM) / 4)    // 1,048,576
#define N4_W2 ((E_NUM * H_DIM * I_DIM) / 4)        //   524,288
#define CONV_BLOCKS ((N4_W1 + N4_W2) / 256)        // 6144 exactly
__global__ __launch_bounds__(256) void ng_conv_kernel(const float* __restrict__ x,
                                                      const float* __restrict__ ns,
                                                      const float* __restrict__ gw,
                                                      const float* __restrict__ gb,
                                                      const float* __restrict__ w1,
                                                      const float* __restrict__ w2,
                                                      float* __restrict__ out) {
    int blk = blockIdx.x;
    if (blk >= T_TOK) {
        int i = (blk - T_TOK) * 256 + threadIdx.x;   // float4 index, < N4_W1+N4_W2
        const float* s; __half* d; int j;
        if (i < N4_W1) { s = w1; d = g_w1h; j = i; }
        else           { s = w2; d = g_w2h; j = i - N4_W1; }
        float4 v = ((const float4*)s)[j];
        ((__half2*)d)[2 * j]     = __floats2half2_rn(v.x, v.y);
        ((__half2*)d)[2 * j + 1] = __floats2half2_rn(v.z, v.w);
        return;
    }
    int t = blk, tid = threadIdx.x, w = tid >> 5, lane = tid & 31;
    __shared__ float ts[H_DIM];
    __shared__ float red[8];
    __shared__ float sl[E_NUM];

    float2 v = ((const float2*)(x + (size_t)t * H_DIM))[tid];
    ((float2*)(out + (size_t)t * H_DIM))[tid] = v;   // residual base for gemm2 atomics
    float ss = v.x * v.x + v.y * v.y;
    #pragma unroll
    for (int o = 16; o; o >>= 1) ss += __shfl_xor_sync(0xffffffffu, ss, o);
    if (lane == 0) red[w] = ss;
    __syncthreads();
    float tot = 0.f;
    #pragma unroll
    for (int i = 0; i < 8; i++) tot += red[i];
    float r = rsqrtf(tot * (1.0f / H_DIM) + 1e-6f);
    float2 sc = ((const float2*)ns)[tid];
    float a = v.x * r * sc.x, b = v.y * r * sc.y;
    ts[2 * tid] = a; ts[2 * tid + 1] = b;
    ((__half2*)(g_th + (size_t)t * H_DIM))[tid] = __floats2half2_rn(a, b);
    __syncthreads();

    float s = 0.f;
    #pragma unroll
    for (int j = 0; j < H_DIM / 32; j++) s += ts[lane + 32 * j] * gw[w * H_DIM + lane + 32 * j];
    #pragma unroll
    for (int o = 16; o; o >>= 1) s += __shfl_xor_sync(0xffffffffu, s, o);
    if (lane == 0) sl[w] = s + gb[w];
    __syncthreads();
    if (tid == 0) {
        float l[E_NUM], p[E_NUM];
        float m = -1e30f;
        #pragma unroll
        for (int e = 0; e < E_NUM; e++) { l[e] = sl[e]; m = fmaxf(m, l[e]); }
        float sum = 0.f;
        #pragma unroll
        for (int e = 0; e < E_NUM; e++) { p[e] = expf(l[e] - m); sum += p[e]; }
        float inv = 1.f / sum;
        #pragma unroll
        for (int e = 0; e < E_NUM; e++) {
            p[e] *= inv;
            atomicAdd(&g_sumP[e], p[e]);
            atomicAdd(&g_imp[e],  l[e]);
        }
        bool used[E_NUM] = {false,false,false,false,false,false,false,false};
        int   idx[KTOP];  float wv[KTOP];  float wsum = 0.f;
        #pragma unroll
        for (int k = 0; k < KTOP; k++) {
            int best = -1; float bv = -1.f;
            #pragma unroll
            for (int e = 0; e < E_NUM; e++)
                if (!used[e] && p[e] > bv) { bv = p[e]; best = e; }
            used[best] = true; idx[k] = best; wv[k] = bv; wsum += bv;
            atomicAdd(&g_wc[best], (float)(16 >> k));
        }
        float winv = 1.f / wsum;
        #pragma unroll
        for (int k = 0; k < KTOP; k++) {
            int e = idx[k];
            int slot = atomicAdd(&g_cnt[e], 1);
            g_tok[e * T_TOK + slot] = t;
            g_cw [e * T_TOK + slot] = wv[k] * winv;
        }
    }
}

// frag loads: A as 4x ldsm_x4 (m16k16), B as 2x ldsm_x4 (two n8 tiles + both k-halves)
#define LOAD_FRAGS(buf, ksv)                                                     \
    do {                                                                         \
        _Pragma("unroll")                                                        \
        for (int mi = 0; mi < 4; mi++)                                           \
            ldsm_x4(a[buf][mi][0], a[buf][mi][1], a[buf][mi][2], a[buf][mi][3],  \
                    sb + aRel[mi] + (ksv) * 32);                                 \
        _Pragma("unroll")                                                        \
        for (int j = 0; j < 2; j++)                                              \
            ldsm_x4(b[buf][2 * j][0], b[buf][2 * j][1],                          \
                    b[buf][2 * j + 1][0], b[buf][2 * j + 1][1],                  \
                    sb + bRel4[j] + (ksv) * 32);                                 \
    } while (0)

// R12-proven mainloop: depth-1 cp.async prefetch, frag double-buffer. NCH = chunk count.
#define MAINLOOP(NCH)                                                            \
    do {                                                                         \
        {                                                                        \
            unsigned ab = smBase + stoff;                                        \
            _Pragma("unroll")                                                    \
            for (int i = 0; i < 4; i++) {                                        \
                cp16(ab + i * 16,               srcA + i * 8);                   \
                cp16(ab + ATILE_BYTES + i * 16, srcB + i * 8);                   \
            }                                                                    \
            cp_commit();                                                         \
        }                                                                        \
        int st = 0;                                                              \
        for (int ch = 0; ch < (NCH); ch++) {                                     \
            if (ch < (NCH) - 1) {                                                \
                int sn = st + 1; if (sn == NSTAGE) sn = 0;                       \
                unsigned ab = smBase + sn * STAGE_BYTES + stoff;                 \
                const __half* pa = srcA + (ch + 1) * BK;                         \
                const __half* pb = srcB + (ch + 1) * BK;                         \
                _Pragma("unroll")                                                \
                for (int i = 0; i < 4; i++) {                                    \
                    cp16(ab + i * 16,               pa + i * 8);                 \
                    cp16(ab + ATILE_BYTES + i * 16, pb + i * 8);                 \
                }                                                                \
                cp_commit();                                                     \
                asm volatile("cp.async.wait_group 1;" ::: "memory");             \
            } else {                                                             \
                asm volatile("cp.async.wait_group 0;" ::: "memory");             \
            }                                                                    \
            __syncthreads();                                                     \
            unsigned sb = smBase + st * STAGE_BYTES;                             \
            unsigned a[2][4][4], b[2][4][2];                                     \
            LOAD_FRAGS(0, 0);                                                    \
            _Pragma("unroll")                                                    \
            for (int ks = 0; ks < 4; ks++) {                                     \
                int cur = ks & 1;                                                \
                if (ks < 3) LOAD_FRAGS(cur ^ 1, ks + 1);                         \
                _Pragma("unroll")                                                \
                for (int mi = 0; mi < 4; mi++)                                   \
                    _Pragma("unroll")                                            \
                    for (int ni = 0; ni < 4; ni++)                               \
                        hmma(acc[mi][ni], a[cur][mi], b[cur][ni]);               \
            }                                                                    \
            if (++st == NSTAGE) st = 0;                                          \
        }                                                                        \
    } while (0)

// ---------------- GEMM1 (mma.sync + cp.async + frag dbuf): SwiGLU -> g_ah fp16 ----------------
// Block 128x128, K=512 in 8 chunks of 64. 8 warps (2m x 4n), warp tile 64x32.
__global__ __launch_bounds__(256, 2) void gemm1_tc(const float* __restrict__ b1) {
    int e = blockIdx.z;
    int nt = g_cnt[e];
    int row0 = blockIdx.x * 128;
    if (row0 >= nt) return;
    int colBase = blockIdx.y * 128;                 // column in 2I space

    extern __shared__ __align__(16) unsigned char sm[];
    unsigned smBase = smem_u32(sm);

    int tid = threadIdx.x, lane = tid & 31, wid = tid >> 5;
    int wm = wid & 1, wn = wid >> 1;

    int lrow = tid >> 1;                            // 0..127
    int lcol = (tid & 1) * 32;
    const __half* srcA;
    const __half* srcB;
    {
        int slot = row0 + lrow; if (slot >= nt) slot = nt - 1;
        int token = g_tok[e * T_TOK + slot];
        srcA = g_th + (size_t)token * H_DIM + lcol;
        srcB = g_w1h + ((size_t)e * (2 * I_DIM) + colBase + lrow) * H_DIM + lcol;
    }
    unsigned stoff = (unsigned)(lrow * LDH + lcol) * 2;

    float acc[4][4][4];
    #pragma unroll
    for (int mi = 0; mi < 4; mi++)
        #pragma unroll
        for (int ni = 0; ni < 4; ni++)
            #pragma unroll
            for (int j = 0; j < 4; j++) acc[mi][ni][j] = 0.f;

    unsigned aRel[4], bRel4[2];
    #pragma unroll
    for (int mi = 0; mi < 4; mi++)
        aRel[mi] = (unsigned)((wm * 64 + mi * 16 + (lane & 15)) * LDH + (lane >> 4) * 8) * 2;
    #pragma unroll
    for (int j = 0; j < 2; j++)
        bRel4[j] = (unsigned)((wn * 32 + j * 16 + (lane & 7) + (lane >> 4) * 8) * LDH
                 + ((lane >> 3) & 1) * 8) * 2 + ATILE_BYTES;

    MAINLOOP(8);

    // epilogue: fused bias + clip + SwiGLU (even/odd col pair lives in c0/c1)
    const float* bias = b1 + e * (2 * I_DIM) + colBase + wn * 32;
    int q  = lane & 3;
    int rr = lane >> 2;
    #pragma unroll
    for (int mi = 0; mi < 4; mi++) {
        #pragma unroll
        for (int h = 0; h < 2; h++) {
            int slot = row0 + wm * 64 + mi * 16 + rr + h * 8;
            if (slot < nt) {
                __half* arow = g_ah + ((size_t)e * T_TOK + slot) * I_DIM
                             + (colBase >> 1) + wn * 16;
                #pragma unroll
                for (int ni = 0; ni < 4; ni++) {
                    float hg = acc[mi][ni][h * 2]     + bias[ni * 8 + q * 2];
                    float hl = acc[mi][ni][h * 2 + 1] + bias[ni * 8 + q * 2 + 1];
                    hg = fminf(fmaxf(hg, -7.f), 7.f);
                    hl = fminf(fmaxf(hl, -7.f), 7.f);
                    float sg = 1.f / (1.f + __expf(-1.702f * hg));
                    arow[ni * 4 + q] = __float2half_rn(hg * sg + (hl + 1.f));
                }
            }
        }
    }
}

// ---------------- GEMM2 (split-K=2, mma.sync + cp.async): out += cw*(a@W2^T + b2) ----------
// grid.y = 4 col-blocks x 2 K-halves. Each CTA computes K/2=256 (4 chunks) and atomically
// accumulates its partial; bias is added by the kz==0 half only (exact).
// Aux loss computed by block (0,0,0) thread 0.
__global__ __launch_bounds__(256, 2) void gemm2_tc(const float* __restrict__ b2,
                                                   float* __restrict__ out, int out_size) {
    if (blockIdx.x == 0 && blockIdx.y == 0 && blockIdx.z == 0 && threadIdx.x == 0) {
        float load = 0.f;
        #pragma unroll
        for (int e = 0; e < E_NUM; e++) {
            float P = g_sumP[e] / (float)T_TOK;
            float D = g_wc[e] / (float)(T_TOK * KTOP);
            load += P * D;
        }
        load *= 0.01f * (float)E_NUM;
        float m = 0.f;
        #pragma unroll
        for (int e = 0; e < E_NUM; e++) m += g_imp[e];
        m *= (1.f / E_NUM);
        float vv = 0.f;
        #pragma unroll
        for (int e = 0; e < E_NUM; e++) { float d = g_imp[e] - m; vv += d * d; }
        vv *= (1.f / (E_NUM - 1));
        float cv = sqrtf(vv) / (m + 1e-6f);
        out[out_size - 1] = 1.0f * (load + 0.01f * cv * cv);
    }

    int e = blockIdx.z;
    int nt = g_cnt[e];
    int row0 = blockIdx.x * 128;
    if (row0 >= nt) return;
    int colBase = (blockIdx.y & 3) * 128;           // column in H space
    int kz = blockIdx.y >> 2;                        // K-half: 0 or 1

    extern __shared__ __align__(16) unsigned char sm[];
    unsigned smBase = smem_u32(sm);

    int tid = threadIdx.x, lane = tid & 31, wid = tid >> 5;
    int wm = wid & 1, wn = wid >> 1;

    int lrow = tid >> 1;
    int lcol = (tid & 1) * 32;
    const __half* srcA;
    const __half* srcB;
    {
        int slot = row0 + lrow; if (slot >= nt) slot = nt - 1;
        srcA = g_ah + ((size_t)e * T_TOK + slot) * I_DIM + kz * (I_DIM / 2) + lcol;
        srcB = g_w2h + ((size_t)e * H_DIM + colBase + lrow) * I_DIM + kz * (I_DIM / 2) + lcol;
    }
    unsigned stoff = (unsigned)(lrow * LDH + lcol) * 2;

    float acc[4][4][4];
    #pragma unroll
    for (int mi = 0; mi < 4; mi++)
        #pragma unroll
        for (int ni = 0; ni < 4; ni++)
            #pragma unroll
            for (int j = 0; j < 4; j++) acc[mi][ni][j] = 0.f;

    unsigned aRel[4], bRel4[2];
    #pragma unroll
    for (int mi = 0; mi < 4; mi++)
        aRel[mi] = (unsigned)((wm * 64 + mi * 16 + (lane & 15)) * LDH + (lane >> 4) * 8) * 2;
    #pragma unroll
    for (int j = 0; j < 2; j++)
        bRel4[j] = (unsigned)((wn * 32 + j * 16 + (lane & 7) + (lane >> 4) * 8) * LDH
                 + ((lane >> 3) & 1) * 8) * 2 + ATILE_BYTES;

    MAINLOOP(4);                                     // K/2 = 256 = 4 chunks

    const float* bias = b2 + e * H_DIM + colBase + wn * 32;
    float bscale = (kz == 0) ? 1.f : 0.f;
    int q  = lane & 3;
    int rr = lane >> 2;
    #pragma unroll
    for (int mi = 0; mi < 4; mi++) {
        #pragma unroll
        for (int h = 0; h < 2; h++) {
            int slot = row0 + wm * 64 + mi * 16 + rr + h * 8;
            if (slot < nt) {
                int token = g_tok[e * T_TOK + slot];
                float cw  = g_cw [e * T_TOK + slot];
                float* orow = out + (size_t)token * H_DIM + colBase + wn * 32;
                #pragma unroll
                for (int ni = 0; ni < 4; ni++) {
                    float v0 = cw * (acc[mi][ni][h * 2]     + bscale * bias[ni * 8 + q * 2]);
                    float v1 = cw * (acc[mi][ni][h * 2 + 1] + bscale * bias[ni * 8 + q * 2 + 1]);
                    red_v2(&orow[ni * 8 + q * 2], v0, v1);
                }
            }
        }
    }
}

// ---------------- launch ----------------
extern "C" void kernel_launch(void* const* d_in, const int* in_sizes, int n_in,
                              void* d_out, int out_size) {
    const float* x  = (const float*)d_in[0];
    const float* ns = (const float*)d_in[1];
    const float* gw = (const float*)d_in[2];
    const float* gb = (const float*)d_in[3];
    const float* w1 = (const float*)d_in[4];
    const float* b1 = (const float*)d_in[5];
    const float* w2 = (const float*)d_in[6];
    const float* b2 = (const float*)d_in[7];
    float* out = (float*)d_out;

    static int smem_set = 0;
    if (!smem_set) {
        cudaFuncSetAttribute(gemm1_tc, cudaFuncAttributeMaxDynamicSharedMemorySize, SMEM_DYN);
        cudaFuncSetAttribute(gemm2_tc, cudaFuncAttributeMaxDynamicSharedMemorySize, SMEM_DYN);
        smem_set = 1;
    }

    init_kernel<<<1, 32>>>();
    ng_conv_kernel<<<T_TOK + CONV_BLOCKS, 256>>>(x, ns, gw, gb, w1, w2, out);

    dim3 g1(T_TOK / 128, (2 * I_DIM) / 128, E_NUM);   // 16 x 8 x 8
    gemm1_tc<<<g1, 256, SMEM_DYN>>>(b1);
    dim3 g2(T_TOK / 128, (H_DIM / 128) * 2, E_NUM);    // 16 x (4 cols x 2 kz) x 8
    gemm2_tc<<<g2, 256, SMEM_DYN>>>(b2, out, out_size);
}

// round 15
// speedup vs baseline: 1.0134x; 1.0134x over previous
#include <cuda_runtime.h>
#include <cuda_fp16.h>
#include <math.h>

#define T_TOK 2048
#define H_DIM 512
#define I_DIM 512
#define E_NUM 8
#define KTOP  4
#define BK    64
#define KPAD  8
#define LDH   (BK + KPAD)                 // 72 halves = 144 B row stride
#define ATILE_BYTES (128 * LDH * 2)       // 18432
#define STAGE_BYTES (2 * ATILE_BYTES)     // A + B per stage = 36864
#define NSTAGE 3
#define SMEM_DYN (NSTAGE * STAGE_BYTES)   // 110592

// ---------------- scratch (device globals, no allocs) ----------------
__device__ __half g_th [T_TOK * H_DIM];                       // RMSNorm out fp16 (gemm1 A)
__device__ __half g_w1h[(size_t)E_NUM * 2 * I_DIM * H_DIM];   // W1 fp16
__device__ __half g_w2h[(size_t)E_NUM * H_DIM * I_DIM];       // W2 fp16
__device__ __half g_ah [(size_t)E_NUM * T_TOK * I_DIM];       // SwiGLU activations fp16
__device__ int    g_cnt[E_NUM];
__device__ int    g_tok[E_NUM * T_TOK];
__device__ float  g_cw [E_NUM * T_TOK];
__device__ float  g_sumP[E_NUM];
__device__ float  g_imp [E_NUM];
__device__ float  g_wc  [E_NUM];

// ---------------- PTX helpers (base compute_103 target: HMMA + LDSM + cp.async) ----------------
__device__ __forceinline__ unsigned smem_u32(const void* p) {
    unsigned r;
    asm("{ .reg .u64 t; cvta.to.shared.u64 t, %1; cvt.u32.u64 %0, t; }" : "=r"(r) : "l"(p));
    return r;
}
__device__ __forceinline__ void cp16(unsigned saddr, const void* gaddr) {
    asm volatile("cp.async.cg.shared.global [%0], [%1], 16;" :: "r"(saddr), "l"(gaddr));
}
__device__ __forceinline__ void cp_commit() {
    asm volatile("cp.async.commit_group;" ::: "memory");
}
__device__ __forceinline__ void ldsm_x4(unsigned& r0, unsigned& r1, unsigned& r2, unsigned& r3,
                                        unsigned addr) {
    asm volatile("ldmatrix.sync.aligned.m8n8.x4.shared.b16 {%0,%1,%2,%3}, [%4];"
                 : "=r"(r0), "=r"(r1), "=r"(r2), "=r"(r3) : "r"(addr));
}
__device__ __forceinline__ void hmma(float* c, const unsigned* a, const unsigned* b) {
    asm volatile("mma.sync.aligned.m16n8k16.row.col.f32.f16.f16.f32 "
                 "{%0,%1,%2,%3}, {%4,%5,%6,%7}, {%8,%9}, {%0,%1,%2,%3};"
                 : "+f"(c[0]), "+f"(c[1]), "+f"(c[2]), "+f"(c[3])
                 : "r"(a[0]), "r"(a[1]), "r"(a[2]), "r"(a[3]), "r"(b[0]), "r"(b[1]));
}
__device__ __forceinline__ void red_v2(float* gaddr, float v0, float v1) {
    asm volatile("red.global.add.v2.f32 [%0], {%1, %2};"
                 :: "l"(gaddr), "f"(v0), "f"(v1) : "memory");
}

// ---------------- init: zero accumulators (tiny) ----------------
__global__ void init_kernel() {
    if (threadIdx.x < E_NUM) {
        g_cnt[threadIdx.x]  = 0;
        g_sumP[threadIdx.x] = 0.f;
        g_imp[threadIdx.x]  = 0.f;
        g_wc[threadIdx.x]   = 0.f;
    }
}

#define N4_W1 ((E_NUM * 2 * I_DIM * H_DIM) / 4)    // 1,048,576
#define N4_W2 ((E_NUM * H_DIM * I_DIM) / 4)        //   524,288
#define CONV1_BLOCKS (N4_W1 / 256)                 // 4096
#define CONV2_BLOCKS (N4_W2 / 256)                 // 2048

// ---------------- W2 conversion (side stream, overlaps ng_conv + gemm1) ----------------
__global__ void w2conv_kernel(const float* __restrict__ w2) {
    int j = blockIdx.x * 256 + threadIdx.x;        // < N4_W2
    float4 v = ((const float4*)w2)[j];
    ((__half2*)g_w2h)[2 * j]     = __floats2half2_rn(v.x, v.y);
    ((__half2*)g_w2h)[2 * j + 1] = __floats2half2_rn(v.z, v.w);
}

// ---------------- fused RMSNorm + gating + out=x + W1 conversion ----------------
__global__ __launch_bounds__(256) void ng_conv_kernel(const float* __restrict__ x,
                                                      const float* __restrict__ ns,
                                                      const float* __restrict__ gw,
                                                      const float* __restrict__ gb,
                                                      const float* __restrict__ w1,
                                                      float* __restrict__ out) {
    int blk = blockIdx.x;
    if (blk >= T_TOK) {
        int j = (blk - T_TOK) * 256 + threadIdx.x;   // float4 index, < N4_W1
        float4 v = ((const float4*)w1)[j];
        ((__half2*)g_w1h)[2 * j]     = __floats2half2_rn(v.x, v.y);
        ((__half2*)g_w1h)[2 * j + 1] = __floats2half2_rn(v.z, v.w);
        return;
    }
    int t = blk, tid = threadIdx.x, w = tid >> 5, lane = tid & 31;
    __shared__ float ts[H_DIM];
    __shared__ float red[8];
    __shared__ float sl[E_NUM];

    float2 v = ((const float2*)(x + (size_t)t * H_DIM))[tid];
    ((float2*)(out + (size_t)t * H_DIM))[tid] = v;   // residual base for gemm2 atomics
    float ss = v.x * v.x + v.y * v.y;
    #pragma unroll
    for (int o = 16; o; o >>= 1) ss += __shfl_xor_sync(0xffffffffu, ss, o);
    if (lane == 0) red[w] = ss;
    __syncthreads();
    float tot = 0.f;
    #pragma unroll
    for (int i = 0; i < 8; i++) tot += red[i];
    float r = rsqrtf(tot * (1.0f / H_DIM) + 1e-6f);
    float2 sc = ((const float2*)ns)[tid];
    float a = v.x * r * sc.x, b = v.y * r * sc.y;
    ts[2 * tid] = a; ts[2 * tid + 1] = b;
    ((__half2*)(g_th + (size_t)t * H_DIM))[tid] = __floats2half2_rn(a, b);
    __syncthreads();

    float s = 0.f;
    #pragma unroll
    for (int j = 0; j < H_DIM / 32; j++) s += ts[lane + 32 * j] * gw[w * H_DIM + lane + 32 * j];
    #pragma unroll
    for (int o = 16; o; o >>= 1) s += __shfl_xor_sync(0xffffffffu, s, o);
    if (lane == 0) sl[w] = s + gb[w];
    __syncthreads();
    if (tid == 0) {
        float l[E_NUM], p[E_NUM];
        float m = -1e30f;
        #pragma unroll
        for (int e = 0; e < E_NUM; e++) { l[e] = sl[e]; m = fmaxf(m, l[e]); }
        float sum = 0.f;
        #pragma unroll
        for (int e = 0; e < E_NUM; e++) { p[e] = expf(l[e] - m); sum += p[e]; }
        float inv = 1.f / sum;
        #pragma unroll
        for (int e = 0; e < E_NUM; e++) {
            p[e] *= inv;
            atomicAdd(&g_sumP[e], p[e]);
            atomicAdd(&g_imp[e],  l[e]);
        }
        bool used[E_NUM] = {false,false,false,false,false,false,false,false};
        int   idx[KTOP];  float wv[KTOP];  float wsum = 0.f;
        #pragma unroll
        for (int k = 0; k < KTOP; k++) {
            int best = -1; float bv = -1.f;
            #pragma unroll
            for (int e = 0; e < E_NUM; e++)
                if (!used[e] && p[e] > bv) { bv = p[e]; best = e; }
            used[best] = true; idx[k] = best; wv[k] = bv; wsum += bv;
            atomicAdd(&g_wc[best], (float)(16 >> k));
        }
        float winv = 1.f / wsum;
        #pragma unroll
        for (int k = 0; k < KTOP; k++) {
            int e = idx[k];
            int slot = atomicAdd(&g_cnt[e], 1);
            g_tok[e * T_TOK + slot] = t;
            g_cw [e * T_TOK + slot] = wv[k] * winv;
        }
    }
}

// frag loads: A as 4x ldsm_x4 (m16k16), B as 2x ldsm_x4 (two n8 tiles + both k-halves)
#define LOAD_FRAGS(buf, ksv)                                                     \
    do {                                                                         \
        _Pragma("unroll")                                                        \
        for (int mi = 0; mi < 4; mi++)                                           \
            ldsm_x4(a[buf][mi][0], a[buf][mi][1], a[buf][mi][2], a[buf][mi][3],  \
                    sb + aRel[mi] + (ksv) * 32);                                 \
        _Pragma("unroll")                                                        \
        for (int j = 0; j < 2; j++)                                              \
            ldsm_x4(b[buf][2 * j][0], b[buf][2 * j][1],                          \
                    b[buf][2 * j + 1][0], b[buf][2 * j + 1][1],                  \
                    sb + bRel4[j] + (ksv) * 32);                                 \
    } while (0)

// R12-proven mainloop: depth-1 cp.async prefetch, frag double-buffer, fully unrolled.
#define MAINLOOP()                                                               \
    do {                                                                         \
        {                                                                        \
            unsigned ab = smBase + stoff;                                        \
            _Pragma("unroll")                                                    \
            for (int i = 0; i < 4; i++) {                                        \
                cp16(ab + i * 16,               srcA + i * 8);                   \
                cp16(ab + ATILE_BYTES + i * 16, srcB + i * 8);                   \
            }                                                                    \
            cp_commit();                                                         \
        }                                                                        \
        _Pragma("unroll")                                                        \
        for (int ch = 0; ch < 8; ch++) {                                         \
            int st = ch % NSTAGE;                                                \
            if (ch < 7) {                                                        \
                int sn = (ch + 1) % NSTAGE;                                      \
                unsigned ab = smBase + sn * STAGE_BYTES + stoff;                 \
                const __half* pa = srcA + (ch + 1) * BK;                         \
                const __half* pb = srcB + (ch + 1) * BK;                         \
                _Pragma("unroll")                                                \
                for (int i = 0; i < 4; i++) {                                    \
                    cp16(ab + i * 16,               pa + i * 8);                 \
                    cp16(ab + ATILE_BYTES + i * 16, pb + i * 8);                 \
                }                                                                \
                cp_commit();                                                     \
                asm volatile("cp.async.wait_group 1;" ::: "memory");             \
            } else {                                                             \
                asm volatile("cp.async.wait_group 0;" ::: "memory");             \
            }                                                                    \
            __syncthreads();                                                     \
            unsigned sb = smBase + st * STAGE_BYTES;                             \
            unsigned a[2][4][4], b[2][4][2];                                     \
            LOAD_FRAGS(0, 0);                                                    \
            _Pragma("unroll")                                                    \
            for (int ks = 0; ks < 4; ks++) {                                     \
                int cur = ks & 1;                                                \
                if (ks < 3) LOAD_FRAGS(cur ^ 1, ks + 1);                         \
                _Pragma("unroll")                                                \
                for (int mi = 0; mi < 4; mi++)                                   \
                    _Pragma("unroll")                                            \
                    for (int ni = 0; ni < 4; ni++)                               \
                        hmma(acc[mi][ni], a[cur][mi], b[cur][ni]);               \
            }                                                                    \
        }                                                                        \
    } while (0)

// ---------------- GEMM1 (mma.sync + cp.async + frag dbuf): SwiGLU -> g_ah fp16 ----------------
// Block 128x128, K=512 in 8 chunks of 64. 8 warps (2m x 4n), warp tile 64x32.
__global__ __launch_bounds__(256, 2) void gemm1_tc(const float* __restrict__ b1) {
    int e = blockIdx.z;
    int nt = g_cnt[e];
    int row0 = blockIdx.x * 128;
    if (row0 >= nt) return;
    int colBase = blockIdx.y * 128;                 // column in 2I space

    extern __shared__ __align__(16) unsigned char sm[];
    unsigned smBase = smem_u32(sm);

    int tid = threadIdx.x, lane = tid & 31, wid = tid >> 5;
    int wm = wid & 1, wn = wid >> 1;

    int lrow = tid >> 1;                            // 0..127
    int lcol = (tid & 1) * 32;
    const __half* srcA;
    const __half* srcB;
    {
        int slot = row0 + lrow; if (slot >= nt) slot = nt - 1;
        int token = g_tok[e * T_TOK + slot];
        srcA = g_th + (size_t)token * H_DIM + lcol;
        srcB = g_w1h + ((size_t)e * (2 * I_DIM) + colBase + lrow) * H_DIM + lcol;
    }
    unsigned stoff = (unsigned)(lrow * LDH + lcol) * 2;

    float acc[4][4][4];
    #pragma unroll
    for (int mi = 0; mi < 4; mi++)
        #pragma unroll
        for (int ni = 0; ni < 4; ni++)
            #pragma unroll
            for (int j = 0; j < 4; j++) acc[mi][ni][j] = 0.f;

    unsigned aRel[4], bRel4[2];
    #pragma unroll
    for (int mi = 0; mi < 4; mi++)
        aRel[mi] = (unsigned)((wm * 64 + mi * 16 + (lane & 15)) * LDH + (lane >> 4) * 8) * 2;
    #pragma unroll
    for (int j = 0; j < 2; j++)
        bRel4[j] = (unsigned)((wn * 32 + j * 16 + (lane & 7) + (lane >> 4) * 8) * LDH
                 + ((lane >> 3) & 1) * 8) * 2 + ATILE_BYTES;

    MAINLOOP();

    // epilogue: fused bias + clip + SwiGLU (even/odd col pair lives in c0/c1)
    const float* bias = b1 + e * (2 * I_DIM) + colBase + wn * 32;
    int q  = lane & 3;
    int rr = lane >> 2;
    #pragma unroll
    for (int mi = 0; mi < 4; mi++) {
        #pragma unroll
        for (int h = 0; h < 2; h++) {
            int slot = row0 + wm * 64 + mi * 16 + rr + h * 8;
            if (slot < nt) {
                __half* arow = g_ah + ((size_t)e * T_TOK + slot) * I_DIM
                             + (colBase >> 1) + wn * 16;
                #pragma unroll
                for (int ni = 0; ni < 4; ni++) {
                    float hg = acc[mi][ni][h * 2]     + bias[ni * 8 + q * 2];
                    float hl = acc[mi][ni][h * 2 + 1] + bias[ni * 8 + q * 2 + 1];
                    hg = fminf(fmaxf(hg, -7.f), 7.f);
                    hl = fminf(fmaxf(hl, -7.f), 7.f);
                    float sg = 1.f / (1.f + __expf(-1.702f * hg));
                    arow[ni * 4 + q] = __float2half_rn(hg * sg + (hl + 1.f));
                }
            }
        }
    }
}

// ---------------- GEMM2 (mma.sync + cp.async + frag dbuf): out += cw*(a@W2^T + b2) ------------
// Aux loss computed by block (0,0,0) thread 0 (inputs ready since ng_conv).
__global__ __launch_bounds__(256, 2) void gemm2_tc(const float* __restrict__ b2,
                                                   float* __restrict__ out, int out_size) {
    if (blockIdx.x == 0 && blockIdx.y == 0 && blockIdx.z == 0 && threadIdx.x == 0) {
        float load = 0.f;
        #pragma unroll
        for (int e = 0; e < E_NUM; e++) {
            float P = g_sumP[e] / (float)T_TOK;
            float D = g_wc[e] / (float)(T_TOK * KTOP);
            load += P * D;
        }
        load *= 0.01f * (float)E_NUM;
        float m = 0.f;
        #pragma unroll
        for (int e = 0; e < E_NUM; e++) m += g_imp[e];
        m *= (1.f / E_NUM);
        float vv = 0.f;
        #pragma unroll
        for (int e = 0; e < E_NUM; e++) { float d = g_imp[e] - m; vv += d * d; }
        vv *= (1.f / (E_NUM - 1));
        float cv = sqrtf(vv) / (m + 1e-6f);
        out[out_size - 1] = 1.0f * (load + 0.01f * cv * cv);
    }

    int e = blockIdx.z;
    int nt = g_cnt[e];
    int row0 = blockIdx.x * 128;
    if (row0 >= nt) return;
    int colBase = blockIdx.y * 128;                 // column in H space

    extern __shared__ __align__(16) unsigned char sm[];
    unsigned smBase = smem_u32(sm);

    int tid = threadIdx.x, lane = tid & 31, wid = tid >> 5;
    int wm = wid & 1, wn = wid >> 1;

    int lrow = tid >> 1;
    int lcol = (tid & 1) * 32;
    const __half* srcA;
    const __half* srcB;
    {
        int slot = row0 + lrow; if (slot >= nt) slot = nt - 1;
        srcA = g_ah + ((size_t)e * T_TOK + slot) * I_DIM + lcol;
        srcB = g_w2h + ((size_t)e * H_DIM + colBase + lrow) * I_DIM + lcol;
    }
    unsigned stoff = (unsigned)(lrow * LDH + lcol) * 2;

    float acc[4][4][4];
    #pragma unroll
    for (int mi = 0; mi < 4; mi++)
        #pragma unroll
        for (int ni = 0; ni < 4; ni++)
            #pragma unroll
            for (int j = 0; j < 4; j++) acc[mi][ni][j] = 0.f;

    unsigned aRel[4], bRel4[2];
    #pragma unroll
    for (int mi = 0; mi < 4; mi++)
        aRel[mi] = (unsigned)((wm * 64 + mi * 16 + (lane & 15)) * LDH + (lane >> 4) * 8) * 2;
    #pragma unroll
    for (int j = 0; j < 2; j++)
        bRel4[j] = (unsigned)((wn * 32 + j * 16 + (lane & 7) + (lane >> 4) * 8) * LDH
                 + ((lane >> 3) & 1) * 8) * 2 + ATILE_BYTES;

    MAINLOOP();

    const float* bias = b2 + e * H_DIM + colBase + wn * 32;
    int q  = lane & 3;
    int rr = lane >> 2;
    #pragma unroll
    for (int mi = 0; mi < 4; mi++) {
        #pragma unroll
        for (int h = 0; h < 2; h++) {
            int slot = row0 + wm * 64 + mi * 16 + rr + h * 8;
            if (slot < nt) {
                int token = g_tok[e * T_TOK + slot];
                float cw  = g_cw [e * T_TOK + slot];
                float* orow = out + (size_t)token * H_DIM + colBase + wn * 32;
                #pragma unroll
                for (int ni = 0; ni < 4; ni++) {
                    float v0 = cw * (acc[mi][ni][h * 2]     + bias[ni * 8 + q * 2]);
                    float v1 = cw * (acc[mi][ni][h * 2 + 1] + bias[ni * 8 + q * 2 + 1]);
                    red_v2(&orow[ni * 8 + q * 2], v0, v1);
                }
            }
        }
    }
}

// ---------------- launch ----------------
extern "C" void kernel_launch(void* const* d_in, const int* in_sizes, int n_in,
                              void* d_out, int out_size) {
    const float* x  = (const float*)d_in[0];
    const float* ns = (const float*)d_in[1];
    const float* gw = (const float*)d_in[2];
    const float* gb = (const float*)d_in[3];
    const float* w1 = (const float*)d_in[4];
    const float* b1 = (const float*)d_in[5];
    const float* w2 = (const float*)d_in[6];
    const float* b2 = (const float*)d_in[7];
    float* out = (float*)d_out;

    static cudaStream_t s_side = 0;
    static cudaEvent_t  s_ev0 = 0, s_ev1 = 0;
    static int inited = 0;
    if (!inited) {
        cudaFuncSetAttribute(gemm1_tc, cudaFuncAttributeMaxDynamicSharedMemorySize, SMEM_DYN);
        cudaFuncSetAttribute(gemm2_tc, cudaFuncAttributeMaxDynamicSharedMemorySize, SMEM_DYN);
        cudaStreamCreateWithFlags(&s_side, cudaStreamNonBlocking);
        cudaEventCreateWithFlags(&s_ev0, cudaEventDisableTiming);
        cudaEventCreateWithFlags(&s_ev1, cudaEventDisableTiming);
        inited = 1;
    }

    // fork: W2 conversion runs on the side stream, overlapped with ng_conv + gemm1
    cudaEventRecord(s_ev0, 0);
    cudaStreamWaitEvent(s_side, s_ev0, 0);
    w2conv_kernel<<<CONV2_BLOCKS, 256, 0, s_side>>>(w2);
    cudaEventRecord(s_ev1, s_side);

    init_kernel<<<1, 32>>>();
    ng_conv_kernel<<<T_TOK + CONV1_BLOCKS, 256>>>(x, ns, gw, gb, w1, out);

    dim3 g1(T_TOK / 128, (2 * I_DIM) / 128, E_NUM);   // 16 x 8 x 8
    gemm1_tc<<<g1, 256, SMEM_DYN>>>(b1);

    // join: gemm2 needs g_w2h
    cudaStreamWaitEvent(0, s_ev1, 0);
    dim3 g2(T_TOK / 128, H_DIM / 128, E_NUM);          // 16 x 4 x 8
    gemm2_tc<<<g2, 256, SMEM_DYN>>>(b2, out, out_size);
}

// round 16
// speedup vs baseline: 1.0545x; 1.0406x over previous
#include <cuda_runtime.h>
#include <cuda_fp16.h>
#include <math.h>

#define T_TOK 2048
#define H_DIM 512
#define I_DIM 512
#define E_NUM 8
#define KTOP  4
#define BK    64
#define KPAD  8
#define LDH   (BK + KPAD)                 // 72 halves = 144 B row stride
#define ATILE_BYTES (128 * LDH * 2)       // 18432
#define STAGE_BYTES (2 * ATILE_BYTES)     // A + B per stage = 36864
#define NSTAGE 3
#define SMEM_DYN (NSTAGE * STAGE_BYTES)   // 110592

// ---------------- scratch (device globals, no allocs) ----------------
__device__ __half g_th [T_TOK * H_DIM];                       // RMSNorm out fp16 (gemm1 A)
__device__ __half g_w1h[(size_t)E_NUM * 2 * I_DIM * H_DIM];   // W1 fp16
__device__ __half g_w2h[(size_t)E_NUM * H_DIM * I_DIM];       // W2 fp16
__device__ __half g_ah [(size_t)E_NUM * T_TOK * I_DIM];       // SwiGLU activations fp16
__device__ int    g_cnt[E_NUM];
__device__ int    g_tok[E_NUM * T_TOK];
__device__ float  g_cw [E_NUM * T_TOK];
__device__ float  g_sumP[E_NUM];
__device__ float  g_imp [E_NUM];
__device__ float  g_wc  [E_NUM];

// ---------------- PTX helpers (base compute_103 target: HMMA + LDSM + cp.async) ----------------
__device__ __forceinline__ unsigned smem_u32(const void* p) {
    unsigned r;
    asm("{ .reg .u64 t; cvta.to.shared.u64 t, %1; cvt.u32.u64 %0, t; }" : "=r"(r) : "l"(p));
    return r;
}
// .ca (L1-cached) — GEMMs are latency-bound and tiles have cross-CTA reuse; L1 hits cut
// the exposed cp.async latency from ~234+ cyc (L2) to ~39 cyc for the second reader.
__device__ __forceinline__ void cp16(unsigned saddr, const void* gaddr) {
    asm volatile("cp.async.ca.shared.global [%0], [%1], 16;" :: "r"(saddr), "l"(gaddr));
}
__device__ __forceinline__ void cp_commit() {
    asm volatile("cp.async.commit_group;" ::: "memory");
}
__device__ __forceinline__ void ldsm_x4(unsigned& r0, unsigned& r1, unsigned& r2, unsigned& r3,
                                        unsigned addr) {
    asm volatile("ldmatrix.sync.aligned.m8n8.x4.shared.b16 {%0,%1,%2,%3}, [%4];"
                 : "=r"(r0), "=r"(r1), "=r"(r2), "=r"(r3) : "r"(addr));
}
__device__ __forceinline__ void hmma(float* c, const unsigned* a, const unsigned* b) {
    asm volatile("mma.sync.aligned.m16n8k16.row.col.f32.f16.f16.f32 "
                 "{%0,%1,%2,%3}, {%4,%5,%6,%7}, {%8,%9}, {%0,%1,%2,%3};"
                 : "+f"(c[0]), "+f"(c[1]), "+f"(c[2]), "+f"(c[3])
                 : "r"(a[0]), "r"(a[1]), "r"(a[2]), "r"(a[3]), "r"(b[0]), "r"(b[1]));
}
__device__ __forceinline__ void red_v2(float* gaddr, float v0, float v1) {
    asm volatile("red.global.add.v2.f32 [%0], {%1, %2};"
                 :: "l"(gaddr), "f"(v0), "f"(v1) : "memory");
}

// ---------------- init: zero accumulators (tiny) ----------------
__global__ void init_kernel() {
    if (threadIdx.x < E_NUM) {
        g_cnt[threadIdx.x]  = 0;
        g_sumP[threadIdx.x] = 0.f;
        g_imp[threadIdx.x]  = 0.f;
        g_wc[threadIdx.x]   = 0.f;
    }
}

// ---------------- fused RMSNorm + gating + out=x + weight conversion ----------------
#define N4_W1 ((E_NUM * 2 * I_DIM * H_DIM) / 4)    // 1,048,576
#define N4_W2 ((E_NUM * H_DIM * I_DIM) / 4)        //   524,288
#define CONV_BLOCKS ((N4_W1 + N4_W2) / 256)        // 6144 exactly
__global__ __launch_bounds__(256) void ng_conv_kernel(const float* __restrict__ x,
                                                      const float* __restrict__ ns,
                                                      const float* __restrict__ gw,
                                                      const float* __restrict__ gb,
                                                      const float* __restrict__ w1,
                                                      const float* __restrict__ w2,
                                                      float* __restrict__ out) {
    int blk = blockIdx.x;
    if (blk >= T_TOK) {
        int i = (blk - T_TOK) * 256 + threadIdx.x;   // float4 index, < N4_W1+N4_W2
        const float* s; __half* d; int j;
        if (i < N4_W1) { s = w1; d = g_w1h; j = i; }
        else           { s = w2; d = g_w2h; j = i - N4_W1; }
        float4 v = ((const float4*)s)[j];
        ((__half2*)d)[2 * j]     = __floats2half2_rn(v.x, v.y);
        ((__half2*)d)[2 * j + 1] = __floats2half2_rn(v.z, v.w);
        return;
    }
    int t = blk, tid = threadIdx.x, w = tid >> 5, lane = tid & 31;
    __shared__ float ts[H_DIM];
    __shared__ float red[8];
    __shared__ float sl[E_NUM];

    float2 v = ((const float2*)(x + (size_t)t * H_DIM))[tid];
    ((float2*)(out + (size_t)t * H_DIM))[tid] = v;   // residual base for gemm2 atomics
    float ss = v.x * v.x + v.y * v.y;
    #pragma unroll
    for (int o = 16; o; o >>= 1) ss += __shfl_xor_sync(0xffffffffu, ss, o);
    if (lane == 0) red[w] = ss;
    __syncthreads();
    float tot = 0.f;
    #pragma unroll
    for (int i = 0; i < 8; i++) tot += red[i];
    float r = rsqrtf(tot * (1.0f / H_DIM) + 1e-6f);
    float2 sc = ((const float2*)ns)[tid];
    float a = v.x * r * sc.x, b = v.y * r * sc.y;
    ts[2 * tid] = a; ts[2 * tid + 1] = b;
    ((__half2*)(g_th + (size_t)t * H_DIM))[tid] = __floats2half2_rn(a, b);
    __syncthreads();

    float s = 0.f;
    #pragma unroll
    for (int j = 0; j < H_DIM / 32; j++) s += ts[lane + 32 * j] * gw[w * H_DIM + lane + 32 * j];
    #pragma unroll
    for (int o = 16; o; o >>= 1) s += __shfl_xor_sync(0xffffffffu, s, o);
    if (lane == 0) sl[w] = s + gb[w];
    __syncthreads();
    if (tid == 0) {
        float l[E_NUM], p[E_NUM];
        float m = -1e30f;
        #pragma unroll
        for (int e = 0; e < E_NUM; e++) { l[e] = sl[e]; m = fmaxf(m, l[e]); }
        float sum = 0.f;
        #pragma unroll
        for (int e = 0; e < E_NUM; e++) { p[e] = expf(l[e] - m); sum += p[e]; }
        float inv = 1.f / sum;
        #pragma unroll
        for (int e = 0; e < E_NUM; e++) {
            p[e] *= inv;
            atomicAdd(&g_sumP[e], p[e]);
            atomicAdd(&g_imp[e],  l[e]);
        }
        bool used[E_NUM] = {false,false,false,false,false,false,false,false};
        int   idx[KTOP];  float wv[KTOP];  float wsum = 0.f;
        #pragma unroll
        for (int k = 0; k < KTOP; k++) {
            int best = -1; float bv = -1.f;
            #pragma unroll
            for (int e = 0; e < E_NUM; e++)
                if (!used[e] && p[e] > bv) { bv = p[e]; best = e; }
            used[best] = true; idx[k] = best; wv[k] = bv; wsum += bv;
            atomicAdd(&g_wc[best], (float)(16 >> k));
        }
        float winv = 1.f / wsum;
        #pragma unroll
        for (int k = 0; k < KTOP; k++) {
            int e = idx[k];
            int slot = atomicAdd(&g_cnt[e], 1);
            g_tok[e * T_TOK + slot] = t;
            g_cw [e * T_TOK + slot] = wv[k] * winv;
        }
    }
}

// frag loads: A as 4x ldsm_x4 (m16k16), B as 2x ldsm_x4 (two n8 tiles + both k-halves)
#define LOAD_FRAGS(buf, ksv)                                                     \
    do {                                                                         \
        _Pragma("unroll")                                                        \
        for (int mi = 0; mi < 4; mi++)                                           \
            ldsm_x4(a[buf][mi][0], a[buf][mi][1], a[buf][mi][2], a[buf][mi][3],  \
                    sb + aRel[mi] + (ksv) * 32);                                 \
        _Pragma("unroll")                                                        \
        for (int j = 0; j < 2; j++)                                              \
            ldsm_x4(b[buf][2 * j][0], b[buf][2 * j][1],                          \
                    b[buf][2 * j + 1][0], b[buf][2 * j + 1][1],                  \
                    sb + bRel4[j] + (ksv) * 32);                                 \
    } while (0)

// R12-proven mainloop: depth-1 cp.async prefetch, frag double-buffer (dynamic loop).
#define MAINLOOP()                                                               \
    do {                                                                         \
        {                                                                        \
            unsigned ab = smBase + stoff;                                        \
            _Pragma("unroll")                                                    \
            for (int i = 0; i < 4; i++) {                                        \
                cp16(ab + i * 16,               srcA + i * 8);                   \
                cp16(ab + ATILE_BYTES + i * 16, srcB + i * 8);                   \
            }                                                                    \
            cp_commit();                                                         \
        }                                                                        \
        int st = 0;                                                              \
        for (int ch = 0; ch < 8; ch++) {                                         \
            if (ch < 7) {                                                        \
                int sn = st + 1; if (sn == NSTAGE) sn = 0;                       \
                unsigned ab = smBase + sn * STAGE_BYTES + stoff;                 \
                const __half* pa = srcA + (ch + 1) * BK;                         \
                const __half* pb = srcB + (ch + 1) * BK;                         \
                _Pragma("unroll")                                                \
                for (int i = 0; i < 4; i++) {                                    \
                    cp16(ab + i * 16,               pa + i * 8);                 \
                    cp16(ab + ATILE_BYTES + i * 16, pb + i * 8);                 \
                }                                                                \
                cp_commit();                                                     \
                asm volatile("cp.async.wait_group 1;" ::: "memory");             \
            } else {                                                             \
                asm volatile("cp.async.wait_group 0;" ::: "memory");             \
            }                                                                    \
            __syncthreads();                                                     \
            unsigned sb = smBase + st * STAGE_BYTES;                             \
            unsigned a[2][4][4], b[2][4][2];                                     \
            LOAD_FRAGS(0, 0);                                                    \
            _Pragma("unroll")                                                    \
            for (int ks = 0; ks < 4; ks++) {                                     \
                int cur = ks & 1;                                                \
                if (ks < 3) LOAD_FRAGS(cur ^ 1, ks + 1);                         \
                _Pragma("unroll")                                                \
                for (int mi = 0; mi < 4; mi++)                                   \
                    _Pragma("unroll")                                            \
                    for (int ni = 0; ni < 4; ni++)                               \
                        hmma(acc[mi][ni], a[cur][mi], b[cur][ni]);               \
            }                                                                    \
            if (++st == NSTAGE) st = 0;                                          \
        }                                                                        \
    } while (0)

// ---------------- GEMM1 (mma.sync + cp.async + frag dbuf): SwiGLU -> g_ah fp16 ----------------
// Block 128x128, K=512 in 8 chunks of 64. 8 warps (2m x 4n), warp tile 64x32.
__global__ __launch_bounds__(256, 2) void gemm1_tc(const float* __restrict__ b1) {
    int e = blockIdx.z;
    int nt = g_cnt[e];
    int row0 = blockIdx.x * 128;
    if (row0 >= nt) return;
    int colBase = blockIdx.y * 128;                 // column in 2I space

    extern __shared__ __align__(16) unsigned char sm[];
    unsigned smBase = smem_u32(sm);

    int tid = threadIdx.x, lane = tid & 31, wid = tid >> 5;
    int wm = wid & 1, wn = wid >> 1;

    int lrow = tid >> 1;                            // 0..127
    int lcol = (tid & 1) * 32;
    const __half* srcA;
    const __half* srcB;
    {
        int slot = row0 + lrow; if (slot >= nt) slot = nt - 1;
        int token = g_tok[e * T_TOK + slot];
        srcA = g_th + (size_t)token * H_DIM + lcol;
        srcB = g_w1h + ((size_t)e * (2 * I_DIM) + colBase + lrow) * H_DIM + lcol;
    }
    unsigned stoff = (unsigned)(lrow * LDH + lcol) * 2;

    float acc[4][4][4];
    #pragma unroll
    for (int mi = 0; mi < 4; mi++)
        #pragma unroll
        for (int ni = 0; ni < 4; ni++)
            #pragma unroll
            for (int j = 0; j < 4; j++) acc[mi][ni][j] = 0.f;

    unsigned aRel[4], bRel4[2];
    #pragma unroll
    for (int mi = 0; mi < 4; mi++)
        aRel[mi] = (unsigned)((wm * 64 + mi * 16 + (lane & 15)) * LDH + (lane >> 4) * 8) * 2;
    #pragma unroll
    for (int j = 0; j < 2; j++)
        bRel4[j] = (unsigned)((wn * 32 + j * 16 + (lane & 7) + (lane >> 4) * 8) * LDH
                 + ((lane >> 3) & 1) * 8) * 2 + ATILE_BYTES;

    MAINLOOP();

    // epilogue: fused bias + clip + SwiGLU (even/odd col pair lives in c0/c1)
    const float* bias = b1 + e * (2 * I_DIM) + colBase + wn * 32;
    int q  = lane & 3;
    int rr = lane >> 2;
    #pragma unroll
    for (int mi = 0; mi < 4; mi++) {
        #pragma unroll
        for (int h = 0; h < 2; h++) {
            int slot = row0 + wm * 64 + mi * 16 + rr + h * 8;
            if (slot < nt) {
                __half* arow = g_ah + ((size_t)e * T_TOK + slot) * I_DIM
                             + (colBase >> 1) + wn * 16;
                #pragma unroll
                for (int ni = 0; ni < 4; ni++) {
                    float hg = acc[mi][ni][h * 2]     + bias[ni * 8 + q * 2];
                    float hl = acc[mi][ni][h * 2 + 1] + bias[ni * 8 + q * 2 + 1];
                    hg = fminf(fmaxf(hg, -7.f), 7.f);
                    hl = fminf(fmaxf(hl, -7.f), 7.f);
                    float sg = 1.f / (1.f + __expf(-1.702f * hg));
                    arow[ni * 4 + q] = __float2half_rn(hg * sg + (hl + 1.f));
                }
            }
        }
    }
}

// ---------------- GEMM2 (mma.sync + cp.async + frag dbuf): out += cw*(a@W2^T + b2) ------------
// Aux loss computed by block (0,0,0) thread 0 (inputs ready since ng_conv).
__global__ __launch_bounds__(256, 2) void gemm2_tc(const float* __restrict__ b2,
                                                   float* __restrict__ out, int out_size) {
    if (blockIdx.x == 0 && blockIdx.y == 0 && blockIdx.z == 0 && threadIdx.x == 0) {
        float load = 0.f;
        #pragma unroll
        for (int e = 0; e < E_NUM; e++) {
            float P = g_sumP[e] / (float)T_TOK;
            float D = g_wc[e] / (float)(T_TOK * KTOP);
            load += P * D;
        }
        load *= 0.01f * (float)E_NUM;
        float m = 0.f;
        #pragma unroll
        for (int e = 0; e < E_NUM; e++) m += g_imp[e];
        m *= (1.f / E_NUM);
        float vv = 0.f;
        #pragma unroll
        for (int e = 0; e < E_NUM; e++) { float d = g_imp[e] - m; vv += d * d; }
        vv *= (1.f / (E_NUM - 1));
        float cv = sqrtf(vv) / (m + 1e-6f);
        out[out_size - 1] = 1.0f * (load + 0.01f * cv * cv);
    }

    int e = blockIdx.z;
    int nt = g_cnt[e];
    int row0 = blockIdx.x * 128;
    if (row0 >= nt) return;
    int colBase = blockIdx.y * 128;                 // column in H space

    extern __shared__ __align__(16) unsigned char sm[];
    unsigned smBase = smem_u32(sm);

    int tid = threadIdx.x, lane = tid & 31, wid = tid >> 5;
    int wm = wid & 1, wn = wid >> 1;

    int lrow = tid >> 1;
    int lcol = (tid & 1) * 32;
    const __half* srcA;
    const __half* srcB;
    {
        int slot = row0 + lrow; if (slot >= nt) slot = nt - 1;
        srcA = g_ah + ((size_t)e * T_TOK + slot) * I_DIM + lcol;
        srcB = g_w2h + ((size_t)e * H_DIM + colBase + lrow) * I_DIM + lcol;
    }
    unsigned stoff = (unsigned)(lrow * LDH + lcol) * 2;

    float acc[4][4][4];
    #pragma unroll
    for (int mi = 0; mi < 4; mi++)
        #pragma unroll
        for (int ni = 0; ni < 4; ni++)
            #pragma unroll
            for (int j = 0; j < 4; j++) acc[mi][ni][j] = 0.f;

    unsigned aRel[4], bRel4[2];
    #pragma unroll
    for (int mi = 0; mi < 4; mi++)
        aRel[mi] = (unsigned)((wm * 64 + mi * 16 + (lane & 15)) * LDH + (lane >> 4) * 8) * 2;
    #pragma unroll
    for (int j = 0; j < 2; j++)
        bRel4[j] = (unsigned)((wn * 32 + j * 16 + (lane & 7) + (lane >> 4) * 8) * LDH
                 + ((lane >> 3) & 1) * 8) * 2 + ATILE_BYTES;

    MAINLOOP();

    const float* bias = b2 + e * H_DIM + colBase + wn * 32;
    int q  = lane & 3;
    int rr = lane >> 2;
    #pragma unroll
    for (int mi = 0; mi < 4; mi++) {
        #pragma unroll
        for (int h = 0; h < 2; h++) {
            int slot = row0 + wm * 64 + mi * 16 + rr + h * 8;
            if (slot < nt) {
                int token = g_tok[e * T_TOK + slot];
                float cw  = g_cw [e * T_TOK + slot];
                float* orow = out + (size_t)token * H_DIM + colBase + wn * 32;
                #pragma unroll
                for (int ni = 0; ni < 4; ni++) {
                    float v0 = cw * (acc[mi][ni][h * 2]     + bias[ni * 8 + q * 2]);
                    float v1 = cw * (acc[mi][ni][h * 2 + 1] + bias[ni * 8 + q * 2 + 1]);
                    red_v2(&orow[ni * 8 + q * 2], v0, v1);
                }
            }
        }
    }
}

// ---------------- launch ----------------
extern "C" void kernel_launch(void* const* d_in, const int* in_sizes, int n_in,
                              void* d_out, int out_size) {
    const float* x  = (const float*)d_in[0];
    const float* ns = (const float*)d_in[1];
    const float* gw = (const float*)d_in[2];
    const float* gb = (const float*)d_in[3];
    const float* w1 = (const float*)d_in[4];
    const float* b1 = (const float*)d_in[5];
    const float* w2 = (const float*)d_in[6];
    const float* b2 = (const float*)d_in[7];
    float* out = (float*)d_out;

    static int smem_set = 0;
    if (!smem_set) {
        cudaFuncSetAttribute(gemm1_tc, cudaFuncAttributeMaxDynamicSharedMemorySize, SMEM_DYN);
        cudaFuncSetAttribute(gemm2_tc, cudaFuncAttributeMaxDynamicSharedMemorySize, SMEM_DYN);
        smem_set = 1;
    }

    init_kernel<<<1, 32>>>();
    ng_conv_kernel<<<T_TOK + CONV_BLOCKS, 256>>>(x, ns, gw, gb, w1, w2, out);

    dim3 g1(T_TOK / 128, (2 * I_DIM) / 128, E_NUM);   // 16 x 8 x 8
    gemm1_tc<<<g1, 256, SMEM_DYN>>>(b1);
    dim3 g2(T_TOK / 128, H_DIM / 128, E_NUM);          // 16 x 4 x 8
    gemm2_tc<<<g2, 256, SMEM_DYN>>>(b2, out, out_size);
}